// round 14
// baseline (speedup 1.0000x reference)
#include <cuda_runtime.h>
#include <cuda_fp16.h>
#include <math.h>
#include <stdint.h>

#define TT   1024
#define BB   4
#define HH   1024
#define EE   512
#define VV   32000
#define MM   (BB*TT)      // 4096 rows

// ---------------- fp32 scratch ----------------
__device__ float g_pre[MM*HH];
__device__ float g_hs [MM*HH];
__device__ float g_v  [MM*HH];
__device__ float g_scores[BB*TT*TT];
__device__ float g_hbuf[2*BB*HH];
__device__ unsigned g_bar;

// ---------------- fp16 scratch ----------------
__device__ __half g_hsA[MM*HH];
__device__ __half g_wqT[HH*HH];
__device__ __half g_wkT[HH*HH];
__device__ __half g_wvT[HH*HH];
__device__ __half g_qA[MM*HH];
__device__ __half g_kB[MM*HH];
__device__ __half g_pA[MM*TT];
__device__ __half g_vT[MM*HH];
__device__ __half g_mixA[(long)MM*2*HH];
__device__ __half g_mixB[(long)HH*2*HH];
__device__ __half g_prA[MM*HH];
__device__ __half g_prB[(long)VV*HH];

// ================= mma.sync helpers =================
__device__ __forceinline__ uint32_t smem_u32(const void* p) {
    uint32_t a;
    asm("{ .reg .u64 t; cvta.to.shared.u64 t, %1; cvt.u32.u64 %0, t; }" : "=r"(a) : "l"(p));
    return a;
}
__device__ __forceinline__ void ldm_x4(uint32_t* r, uint32_t addr) {
    asm volatile("ldmatrix.sync.aligned.m8n8.x4.shared.b16 {%0,%1,%2,%3}, [%4];"
                 : "=r"(r[0]), "=r"(r[1]), "=r"(r[2]), "=r"(r[3]) : "r"(addr));
}
__device__ __forceinline__ void mma16816(float* d, const uint32_t* a, const uint32_t* b) {
    asm volatile(
        "mma.sync.aligned.m16n8k16.row.col.f32.f16.f16.f32 "
        "{%0,%1,%2,%3}, {%4,%5,%6,%7}, {%8,%9}, {%0,%1,%2,%3};"
        : "+f"(d[0]), "+f"(d[1]), "+f"(d[2]), "+f"(d[3])
        : "r"(a[0]), "r"(a[1]), "r"(a[2]), "r"(a[3]), "r"(b[0]), "r"(b[1]));
}
// fp16-accumulator variant: D (f16) = A*B + 0, widened & accumulated in fp32 regs.
__device__ __forceinline__ void mma16816_h(float* d, const uint32_t* a, const uint32_t* b) {
    uint32_t d0, d1;
    const uint32_t z = 0;
    asm volatile(
        "mma.sync.aligned.m16n8k16.row.col.f16.f16.f16.f16 "
        "{%0,%1}, {%2,%3,%4,%5}, {%6,%7}, {%8,%8};"
        : "=r"(d0), "=r"(d1)
        : "r"(a[0]), "r"(a[1]), "r"(a[2]), "r"(a[3]), "r"(b[0]), "r"(b[1]), "r"(z));
    float2 lo = __half22float2(*reinterpret_cast<__half2*>(&d0));
    float2 hi = __half22float2(*reinterpret_cast<__half2*>(&d1));
    d[0] += lo.x; d[1] += lo.y; d[2] += hi.x; d[3] += hi.y;
}
__device__ __forceinline__ void cp16(uint32_t dst, const void* src) {
    asm volatile("cp.async.cg.shared.global [%0], [%1], 16;" :: "r"(dst), "l"(src));
}
#define CP_COMMIT() asm volatile("cp.async.commit_group;" ::: "memory")
#define CP_WAIT1()  asm volatile("cp.async.wait_group 1;"  ::: "memory")
#define CP_WAIT0()  asm volatile("cp.async.wait_group 0;"  ::: "memory")

// ================= fp16 HMMA GEMM 128x128, cp.async 2-stage (proven) =================
// A: [M,K] K-major fp16.  B: [N,K] K-major fp16.
// OMODE 0: C fp32 (+bias/tanh).  OMODE 1: fp16 out (+bias/tanh).
// CAUSAL: skip tiles with n0 > m0+127.  CK: limit K to m0+128.  SWAPXY: m-tile fastest.
// FACC: per-MMA fp16 D (potential 2x tensor rate), fp32 cross-K accumulation.
#define LDS   40         // smem row stride in halves (80B, 16B-aligned, conflict-free)
#define OFF_B 10240
#define STG   20480
#define SMEM_PIPE (2*STG)

template<int OMODE, bool BIAS, bool TANH_ACT, bool CAUSAL, bool CK, bool SWAPXY, bool FACC>
__global__ void __launch_bounds__(256, 2)
tgemm(const __half* __restrict__ A, const __half* __restrict__ B,
      float* __restrict__ C, __half* __restrict__ O,
      const float* __restrict__ bias,
      int M, int N, int K, long batA, long batB, long batC, long batO, int ldo, int coff)
{
    const int m0 = (SWAPXY ? blockIdx.x : blockIdx.y) * 128;
    const int n0 = (SWAPXY ? blockIdx.y : blockIdx.x) * 128;
    if (CAUSAL && n0 > m0 + 127) return;    // tile fully above the causal diagonal

    extern __shared__ char dsm[];
    const uint32_t sbase = smem_u32(dsm);

    const int tid  = threadIdx.x;
    const int wid  = tid >> 5;
    const int lane = tid & 31;
    const int warp_m = wid & 1;
    const int warp_n = wid >> 1;
    const int z  = blockIdx.z;
    A += (long)z * batA;
    B += (long)z * batB;

    float acc[4][4][4];
#pragma unroll
    for (int i = 0; i < 4; i++)
#pragma unroll
        for (int j = 0; j < 4; j++)
#pragma unroll
            for (int r = 0; r < 4; r++) acc[i][j][r] = 0.f;

    const int a_r = lane & 15;
    const int a_c = ((lane >> 4) & 1) * 8;
    const int b_r = (lane & 7) + ((lane >> 4) & 1) * 8;
    const int b_c = ((lane >> 3) & 1) * 8;

    const int lrow = tid >> 1;
    const int lhalf = (tid & 1);
    const uint32_t dstrow = (uint32_t)(lrow * 80 + lhalf * 32);

    const int Keff = CK ? ((m0 + 128) < K ? (m0 + 128) : K) : K;
    const int nchunks = Keff / 32;

    auto issue = [&](int ch, int buf) {
        const long ka = (long)(m0 + lrow) * K + (long)ch * 32 + lhalf * 16;
        const long kb = (long)(n0 + lrow) * K + (long)ch * 32 + lhalf * 16;
        uint32_t d = sbase + buf * STG + dstrow;
        cp16(d,              A + ka);  cp16(d + 16,          A + ka + 8);
        cp16(d + OFF_B,      B + kb);  cp16(d + OFF_B + 16,  B + kb + 8);
    };

    issue(0, 0);
    CP_COMMIT();

    for (int ch = 0; ch < nchunks; ch++) {
        const int buf = ch & 1;
        if (ch + 1 < nchunks) {
            issue(ch + 1, buf ^ 1);
            CP_COMMIT();
            CP_WAIT1();
        } else {
            CP_WAIT0();
        }
        __syncthreads();

        const uint32_t uA = sbase + buf * STG;
        const uint32_t uB = uA + OFF_B;

#pragma unroll
        for (int ks = 0; ks < 2; ks++) {
            uint32_t am[4][4];
#pragma unroll
            for (int ma = 0; ma < 4; ma++) {
                uint32_t off = ((warp_m * 64 + ma * 16 + a_r) * LDS + ks * 16 + a_c) * 2;
                ldm_x4(am[ma], uA + off);
            }
            uint32_t bm[4][2];
#pragma unroll
            for (int np = 0; np < 2; np++) {
                uint32_t off = ((warp_n * 32 + np * 16 + b_r) * LDS + ks * 16 + b_c) * 2;
                uint32_t t[4];
                ldm_x4(t, uB + off);
                bm[np*2][0]   = t[0]; bm[np*2][1]   = t[1];
                bm[np*2+1][0] = t[2]; bm[np*2+1][1] = t[3];
            }
#pragma unroll
            for (int ma = 0; ma < 4; ma++)
#pragma unroll
                for (int na = 0; na < 4; na++) {
                    if (FACC) mma16816_h(acc[ma][na], am[ma], bm[na]);
                    else      mma16816  (acc[ma][na], am[ma], bm[na]);
                }
        }
        __syncthreads();
    }

    if (OMODE == 0) C += (long)z * batC;
    else            O += (long)z * batO;

#pragma unroll
    for (int ma = 0; ma < 4; ma++) {
        const int row0 = m0 + warp_m * 64 + ma * 16 + (lane >> 2);
#pragma unroll
        for (int na = 0; na < 4; na++) {
            const int col = n0 + warp_n * 32 + na * 8 + (lane & 3) * 2;
            float2 v0 = make_float2(acc[ma][na][0], acc[ma][na][1]);
            float2 v1 = make_float2(acc[ma][na][2], acc[ma][na][3]);
            if (BIAS) {
                float2 bb = *reinterpret_cast<const float2*>(bias + col);
                v0.x += bb.x; v0.y += bb.y; v1.x += bb.x; v1.y += bb.y;
            }
            if (TANH_ACT) {
                v0.x = tanhf(v0.x); v0.y = tanhf(v0.y);
                v1.x = tanhf(v1.x); v1.y = tanhf(v1.y);
            }
            if (OMODE == 0) {
                *reinterpret_cast<float2*>(C + (long)row0 * N + col)       = v0;
                *reinterpret_cast<float2*>(C + (long)(row0 + 8) * N + col) = v1;
            } else {
                long o0 = (long)row0 * ldo + coff + col;
                long o1 = (long)(row0 + 8) * ldo + coff + col;
                *reinterpret_cast<__half2*>(O + o0) =
                    __halves2half2(__float2half_rn(v0.x), __float2half_rn(v0.y));
                *reinterpret_cast<__half2*>(O + o1) =
                    __halves2half2(__float2half_rn(v1.x), __float2half_rn(v1.y));
            }
        }
    }
}

// ================= fp32 -> fp16: single read, dual layout write =================
__global__ void __launch_bounds__(256)
conv_R2(const float* __restrict__ in, __half* __restrict__ o1, __half* __restrict__ o2,
        long n, int ld2)
{
    const long n8 = n >> 3;
    for (long i8 = (long)blockIdx.x * 256 + threadIdx.x; i8 < n8; i8 += (long)gridDim.x * 256) {
        long idx = i8 << 3;
        long r = idx >> 10;
        int  c = (int)(idx & 1023);
        float4 x0 = *reinterpret_cast<const float4*>(in + idx);
        float4 x1 = *reinterpret_cast<const float4*>(in + idx + 4);
        alignas(16) __half hv[8];
        hv[0] = __float2half_rn(x0.x); hv[1] = __float2half_rn(x0.y);
        hv[2] = __float2half_rn(x0.z); hv[3] = __float2half_rn(x0.w);
        hv[4] = __float2half_rn(x1.x); hv[5] = __float2half_rn(x1.y);
        hv[6] = __float2half_rn(x1.z); hv[7] = __float2half_rn(x1.w);
        uint4 pk = *reinterpret_cast<const uint4*>(hv);
        *reinterpret_cast<uint4*>(o1 + idx)               = pk;
        *reinterpret_cast<uint4*>(o2 + r * ld2 + c)       = pk;
    }
}

// transpose: in [R,C] fp32 -> out [C,R] fp16 (batched via z)
__global__ void __launch_bounds__(256)
conv_T(const float* __restrict__ in, __half* __restrict__ o, int R, int C, long batIn, long batOut)
{
    __shared__ float t[32][33];
    const int tx = threadIdx.x & 31, ty = threadIdx.x >> 5;
    const int x = blockIdx.x * 32 + tx;
    in += (long)blockIdx.z * batIn;
#pragma unroll
    for (int j = 0; j < 4; j++) {
        int y = blockIdx.y * 32 + ty + j * 8;
        t[ty + j * 8][tx] = in[(long)y * C + x];
    }
    __syncthreads();
    const int ox = blockIdx.y * 32 + tx;
    long ob = (long)blockIdx.z * batOut;
#pragma unroll
    for (int j = 0; j < 4; j++) {
        int oy = blockIdx.x * 32 + ty + j * 8;
        o[ob + (long)oy * R + ox] = __float2half_rn(t[tx][ty + j * 8]);
    }
}

// ================= fp32 gather GEMM (embedding; also resets RNN barrier) =================
template<bool GATHER>
__global__ void __launch_bounds__(256)
gemm128(const float* __restrict__ A, const float* __restrict__ Bm,
        float* __restrict__ C, const float* __restrict__ bias,
        const int* __restrict__ gidx, int M, int N, int K)
{
    const int bx = blockIdx.x, by = blockIdx.y;
    if (bx == 0 && by == 0 && threadIdx.x == 0) g_bar = 0u;   // reset RNN grid barrier
    __shared__ float As[16][128];
    __shared__ float Bs[16][128];
    const int tid = threadIdx.x;
    const int tx = tid & 15, ty = tid >> 4;
    const int m0 = by * 128, n0 = bx * 128;
    float acc[8][8];
#pragma unroll
    for (int i = 0; i < 8; i++)
#pragma unroll
        for (int j = 0; j < 8; j++) acc[i][j] = 0.f;
    for (int kt = 0; kt < K; kt += 16) {
#pragma unroll
        for (int s = 0; s < 2; s++) {
            int id = tid * 2 + s;
            int m = id >> 2, k4 = (id & 3) * 4;
            long arow = GATHER ? (long)gidx[m0 + m] * K : (long)(m0 + m) * K;
            float4 v = *reinterpret_cast<const float4*>(&A[arow + kt + k4]);
            As[k4 + 0][m] = v.x; As[k4 + 1][m] = v.y; As[k4 + 2][m] = v.z; As[k4 + 3][m] = v.w;
        }
#pragma unroll
        for (int s = 0; s < 2; s++) {
            int id = tid * 2 + s;
            int kk = id >> 5, n4 = (id & 31) * 4;
            float4 v = *reinterpret_cast<const float4*>(&Bm[(long)(kt + kk) * N + n0 + n4]);
            *reinterpret_cast<float4*>(&Bs[kk][n4]) = v;
        }
        __syncthreads();
#pragma unroll
        for (int kk = 0; kk < 16; kk++) {
            float a[8], b[8];
            *reinterpret_cast<float4*>(&a[0]) = *reinterpret_cast<const float4*>(&As[kk][ty * 8]);
            *reinterpret_cast<float4*>(&a[4]) = *reinterpret_cast<const float4*>(&As[kk][ty * 8 + 4]);
            *reinterpret_cast<float4*>(&b[0]) = *reinterpret_cast<const float4*>(&Bs[kk][tx * 8]);
            *reinterpret_cast<float4*>(&b[4]) = *reinterpret_cast<const float4*>(&Bs[kk][tx * 8 + 4]);
#pragma unroll
            for (int i = 0; i < 8; i++)
#pragma unroll
                for (int j = 0; j < 8; j++) acc[i][j] = fmaf(a[i], b[j], acc[i][j]);
        }
        __syncthreads();
    }
#pragma unroll
    for (int i = 0; i < 8; i++) {
        long crow = (long)(m0 + ty * 8 + i) * N + n0 + tx * 8;
#pragma unroll
        for (int j = 0; j < 8; j += 4) {
            float4 v = make_float4(acc[i][j], acc[i][j+1], acc[i][j+2], acc[i][j+3]);
            int nb = n0 + tx * 8 + j;
            v.x += bias[nb]; v.y += bias[nb+1]; v.z += bias[nb+2]; v.w += bias[nb+3];
            *reinterpret_cast<float4*>(&C[crow + j]) = v;
        }
    }
}

// ================= RNN recurrence (persistent, 128 CTAs x 256 thr) =================
// Release/acquire grid barrier; pre[t] prefetched off the dependency chain.
#define RNN_CTAS 128

__device__ __forceinline__ void grid_barrier(unsigned phase)
{
    __syncthreads();
    if (threadIdx.x == 0) {
        asm volatile("red.release.gpu.global.add.u32 [%0], %1;"
                     :: "l"(&g_bar), "r"(1u) : "memory");
        const unsigned target = phase * RNN_CTAS;
        unsigned v;
        do {
            asm volatile("ld.acquire.gpu.global.u32 %0, [%1];"
                         : "=r"(v) : "l"(&g_bar) : "memory");
        } while (v < target);
    }
    __syncthreads();
}

__global__ void __launch_bounds__(256, 1)
rnn_kernel(const float* __restrict__ w_hh)
{
    const int c = blockIdx.x, tid = threadIdx.x;
    const int w = tid >> 5, l = tid & 31;
    const int j = c * 8 + w;
    float wr[32];
#pragma unroll
    for (int r = 0; r < 32; r++) wr[r] = w_hh[(long)(r * 32 + l) * HH + j];
    __shared__ float hsm[BB * HH];
    if (l == 0) {
#pragma unroll
        for (int b = 0; b < BB; b++) {
            float hv = tanhf(g_pre[((long)b * TT) * HH + j]);
            __stcg(&g_hbuf[1 * BB * HH + b * HH + j], hv);   // critical path first
            g_hs[((long)b * TT) * HH + j] = hv;
        }
    }
    grid_barrier(1);
    for (int t = 1; t < TT; t++) {
        // prefetch pre[t] (independent of h) so its latency overlaps staging+sync
        float pre_t[BB];
        if (l == 0) {
#pragma unroll
            for (int b = 0; b < BB; b++)
                pre_t[b] = __ldcg(&g_pre[((long)b * TT + t) * HH + j]);
        }

        const float4* src = reinterpret_cast<const float4*>(&g_hbuf[(t & 1) * BB * HH]);
        for (int i = tid; i < BB * HH / 4; i += 256)
            reinterpret_cast<float4*>(hsm)[i] = __ldcg(src + i);
        __syncthreads();
#pragma unroll
        for (int b = 0; b < BB; b++) {
            const float* hp = &hsm[b * HH];
            float s = 0.f;
#pragma unroll
            for (int r = 0; r < 32; r++) s = fmaf(wr[r], hp[r * 32 + l], s);
#pragma unroll
            for (int o = 16; o; o >>= 1) s += __shfl_xor_sync(0xffffffffu, s, o);
            if (l == 0) {
                float hv = tanhf(pre_t[b] + s);
                __stcg(&g_hbuf[((t + 1) & 1) * BB * HH + b * HH + j], hv);  // critical first
                g_hs[((long)b * TT + t) * HH + j] = hv;
            }
        }
        if (t < TT - 1) grid_barrier((unsigned)(t + 1));
    }
}

// ================= causal softmax (fused fp16 store of P) =================
__global__ void __launch_bounds__(256)
softmax_kernel(float* __restrict__ sc)
{
    const int row = blockIdx.x;
    const int t = row & (TT - 1);
    float* p = sc + (long)row * TT;
    __half* ph = g_pA + (long)row * TT;
    __shared__ float red[256];
    const int tid = threadIdx.x;
    const float scale = 1.0f / 32.0f;
    float mx = -1e30f;
    for (int s = tid; s <= t; s += 256) mx = fmaxf(mx, p[s]);
    red[tid] = mx; __syncthreads();
    for (int o = 128; o; o >>= 1) { if (tid < o) red[tid] = fmaxf(red[tid], red[tid + o]); __syncthreads(); }
    mx = red[0] * scale; __syncthreads();
    float sum = 0.f;
    for (int s = tid; s <= t; s += 256) { float e = expf(p[s] * scale - mx); p[s] = e; sum += e; }
    red[tid] = sum; __syncthreads();
    for (int o = 128; o; o >>= 1) { if (tid < o) red[tid] += red[tid + o]; __syncthreads(); }
    const float inv = 1.0f / red[0];
    const __half z16 = __float2half(0.f);
    for (int s = tid; s <= t; s += 256) ph[s] = __float2half_rn(p[s] * inv);
    for (int s = t + 1 + tid; s < TT; s += 256) ph[s] = z16;
}

// ================= launch =================
extern "C" void kernel_launch(void* const* d_in, const int* in_sizes, int n_in,
                              void* d_out, int out_size)
{
    (void)in_sizes; (void)n_in; (void)out_size;
    const int*   x      = (const int*)  d_in[0];
    const float* emb    = (const float*)d_in[1];
    const float* w_ih   = (const float*)d_in[2];
    const float* b_ih   = (const float*)d_in[3];
    const float* w_hh   = (const float*)d_in[4];
    const float* wq     = (const float*)d_in[5];
    const float* wk     = (const float*)d_in[6];
    const float* wv     = (const float*)d_in[7];
    const float* w_mix  = (const float*)d_in[8];
    const float* b_mix  = (const float*)d_in[9];
    const float* w_proj = (const float*)d_in[10];
    const float* b_proj = (const float*)d_in[11];
    float* out = (float*)d_out;

    float *pre, *hs, *v, *scores;
    cudaGetSymbolAddress((void**)&pre, g_pre);
    cudaGetSymbolAddress((void**)&hs, g_hs);
    cudaGetSymbolAddress((void**)&v, g_v);
    cudaGetSymbolAddress((void**)&scores, g_scores);

    __half *hsA,*wqT,*wkT,*wvT,*qA,*kB,*pA,*vT,*mxA,*mxB,*prA,*prB;
    cudaGetSymbolAddress((void**)&hsA, g_hsA);
    cudaGetSymbolAddress((void**)&wqT, g_wqT);
    cudaGetSymbolAddress((void**)&wkT, g_wkT);
    cudaGetSymbolAddress((void**)&wvT, g_wvT);
    cudaGetSymbolAddress((void**)&qA,  g_qA);
    cudaGetSymbolAddress((void**)&kB,  g_kB);
    cudaGetSymbolAddress((void**)&pA,  g_pA);
    cudaGetSymbolAddress((void**)&vT,  g_vT);
    cudaGetSymbolAddress((void**)&mxA, g_mixA);
    cudaGetSymbolAddress((void**)&mxB, g_mixB);
    cudaGetSymbolAddress((void**)&prA, g_prA);
    cudaGetSymbolAddress((void**)&prB, g_prB);

    cudaFuncSetAttribute(tgemm<0,false,false,false,false,false,false>, cudaFuncAttributeMaxDynamicSharedMemorySize, SMEM_PIPE);
    cudaFuncSetAttribute(tgemm<0,false,false,true,false,false,false>,  cudaFuncAttributeMaxDynamicSharedMemorySize, SMEM_PIPE);
    cudaFuncSetAttribute(tgemm<0,true,false,false,false,true,true>,    cudaFuncAttributeMaxDynamicSharedMemorySize, SMEM_PIPE);
    cudaFuncSetAttribute(tgemm<1,false,false,false,false,false,false>, cudaFuncAttributeMaxDynamicSharedMemorySize, SMEM_PIPE);
    cudaFuncSetAttribute(tgemm<1,false,false,false,true,false,false>,  cudaFuncAttributeMaxDynamicSharedMemorySize, SMEM_PIPE);
    cudaFuncSetAttribute(tgemm<1,true,true,false,false,false,false>,   cudaFuncAttributeMaxDynamicSharedMemorySize, SMEM_PIPE);

    dim3 blk(256);
    dim3 tblk(256);

    // Launch order puts rnn_kernel at slot #4 (the one ncu's window captured last round).
    // 1-2) two weight transposes (independent of everything downstream)
    conv_T<<<dim3(HH/32, HH/32), tblk>>>(wq, wqT, HH, HH, 0, 0);
    conv_T<<<dim3(HH/32, HH/32), tblk>>>(wk, wkT, HH, HH, 0, 0);

    // 3) pre = emb[x] @ w_ih + b_ih   (fp32, gather; also resets g_bar)
    gemm128<true><<<dim3(HH/128, MM/128), blk>>>(emb, w_ih, pre, b_ih, x, MM, HH, EE);

    // 4) RNN -> hs (fp32)
    rnn_kernel<<<RNN_CTAS, 256>>>(w_hh);

    // conversions (off the recurrence critical path): hs -> hsA + mixA[:, :H] in one pass
    conv_R2<<<2048, 256>>>(hs, hsA, mxA, (long)MM*HH, 2*HH);
    conv_T<<<dim3(HH/32, HH/32), tblk>>>(wv, wvT, HH, HH, 0, 0);

    // q,k (fp16 out), v (fp32 for transpose)
    tgemm<1,false,false,false,false,false,false><<<dim3(HH/128, MM/128), blk, SMEM_PIPE>>>(
        hsA, wqT, nullptr, qA, nullptr, MM, HH, HH, 0, 0, 0, 0, HH, 0);
    tgemm<1,false,false,false,false,false,false><<<dim3(HH/128, MM/128), blk, SMEM_PIPE>>>(
        hsA, wkT, nullptr, kB, nullptr, MM, HH, HH, 0, 0, 0, 0, HH, 0);
    tgemm<0,false,false,false,false,false,false><<<dim3(HH/128, MM/128), blk, SMEM_PIPE>>>(
        hsA, wvT, v, nullptr, nullptr, MM, HH, HH, 0, 0, 0, 0, 0, 0);

    // scores = q @ k^T (fp32 out, causal tile-skip)
    tgemm<0,false,false,true,false,false,false><<<dim3(TT/128, TT/128, BB), blk, SMEM_PIPE>>>(
        qA, kB, scores, nullptr, nullptr, TT, TT, HH,
        (long)TT*HH, (long)TT*HH, (long)TT*TT, 0, 0, 0);

    // softmax (scale + causal + fp16 P)
    softmax_kernel<<<MM, 256>>>(scores);

    // ctx = P @ V  (causal K-limit) -> fp16 directly into mixA[:, H:2H]
    conv_T<<<dim3(HH/32, TT/32, BB), tblk>>>(v, vT, TT, HH, (long)TT*HH, (long)HH*TT);
    tgemm<1,false,false,false,true,false,false><<<dim3(HH/128, TT/128, BB), blk, SMEM_PIPE>>>(
        pA, vT, nullptr, mxA, nullptr, TT, HH, TT,
        (long)TT*TT, (long)HH*TT, 0, (long)TT*2*HH, 2*HH, HH);

    // h2 = tanh([hs|ctx] @ w_mix + b_mix) -> fp16 into prA
    conv_T<<<dim3(HH/32, 2*HH/32), tblk>>>(w_mix, mxB, 2*HH, HH, 0, 0);
    tgemm<1,true,true,false,false,false,false><<<dim3(HH/128, MM/128), blk, SMEM_PIPE>>>(
        mxA, mxB, nullptr, prA, b_mix, MM, HH, 2*HH, 0, 0, 0, 0, HH, 0);

    // out = h2 @ w_proj + b_proj   (SWAPXY + fp16-acc MMA experiment)
    conv_T<<<dim3(VV/32, HH/32), tblk>>>(w_proj, prB, HH, VV, 0, 0);
    tgemm<0,true,false,false,false,true,true><<<dim3(MM/128, VV/128), blk, SMEM_PIPE>>>(
        prA, prB, out, nullptr, b_proj, MM, VV, HH, 0, 0, 0, 0, 0, 0);
}

// round 17
// speedup vs baseline: 1.0799x; 1.0799x over previous
#include <cuda_runtime.h>
#include <cuda_fp16.h>
#include <math.h>
#include <stdint.h>

#define TT   1024
#define BB   4
#define HH   1024
#define EE   512
#define VV   32000
#define MM   (BB*TT)      // 4096 rows

// ---------------- fp32 scratch ----------------
__device__ float g_pre[MM*HH];
__device__ float g_hs [MM*HH];
__device__ float g_v  [MM*HH];
__device__ float g_scores[BB*TT*TT];
__device__ float g_hbuf[2*BB*HH];
__device__ unsigned g_bar;

// ---------------- fp16 scratch ----------------
__device__ __half g_eA [MM*EE];
__device__ __half g_wihT[HH*EE];
__device__ __half g_hsA[MM*HH];
__device__ __half g_wqT[HH*HH];
__device__ __half g_wkT[HH*HH];
__device__ __half g_wvT[HH*HH];
__device__ __half g_qA[MM*HH];
__device__ __half g_kB[MM*HH];
__device__ __half g_pA[MM*TT];
__device__ __half g_vT[MM*HH];
__device__ __half g_mixA[(long)MM*2*HH];
__device__ __half g_mixB[(long)HH*2*HH];
__device__ __half g_prA[MM*HH];
__device__ __half g_prB[(long)VV*HH];

// ================= mma.sync helpers =================
__device__ __forceinline__ uint32_t smem_u32(const void* p) {
    uint32_t a;
    asm("{ .reg .u64 t; cvta.to.shared.u64 t, %1; cvt.u32.u64 %0, t; }" : "=r"(a) : "l"(p));
    return a;
}
__device__ __forceinline__ void ldm_x4(uint32_t* r, uint32_t addr) {
    asm volatile("ldmatrix.sync.aligned.m8n8.x4.shared.b16 {%0,%1,%2,%3}, [%4];"
                 : "=r"(r[0]), "=r"(r[1]), "=r"(r[2]), "=r"(r[3]) : "r"(addr));
}
__device__ __forceinline__ void mma16816(float* d, const uint32_t* a, const uint32_t* b) {
    asm volatile(
        "mma.sync.aligned.m16n8k16.row.col.f32.f16.f16.f32 "
        "{%0,%1,%2,%3}, {%4,%5,%6,%7}, {%8,%9}, {%0,%1,%2,%3};"
        : "+f"(d[0]), "+f"(d[1]), "+f"(d[2]), "+f"(d[3])
        : "r"(a[0]), "r"(a[1]), "r"(a[2]), "r"(a[3]), "r"(b[0]), "r"(b[1]));
}
__device__ __forceinline__ void cp16(uint32_t dst, const void* src) {
    asm volatile("cp.async.cg.shared.global [%0], [%1], 16;" :: "r"(dst), "l"(src));
}
#define CP_COMMIT() asm volatile("cp.async.commit_group;" ::: "memory")
#define CP_WAIT1()  asm volatile("cp.async.wait_group 1;"  ::: "memory")
#define CP_WAIT0()  asm volatile("cp.async.wait_group 0;"  ::: "memory")

// ================= fp16 HMMA GEMM 128x128, cp.async 2-stage (proven) =================
// A: [M,K] K-major fp16.  B: [N,K] K-major fp16.
// OMODE 0: C fp32 (+bias/tanh).  OMODE 1: fp16 out (+bias/tanh).
// CAUSAL: skip tiles with n0 > m0+127.  CK: limit K to m0+128.  SWAPXY: m-tile fastest.
#define LDS   40         // smem row stride in halves (80B, 16B-aligned, conflict-free)
#define OFF_B 10240
#define STG   20480
#define SMEM_PIPE (2*STG)

template<int OMODE, bool BIAS, bool TANH_ACT, bool CAUSAL, bool CK, bool SWAPXY>
__global__ void __launch_bounds__(256, 2)
tgemm(const __half* __restrict__ A, const __half* __restrict__ B,
      float* __restrict__ C, __half* __restrict__ O,
      const float* __restrict__ bias,
      int M, int N, int K, long batA, long batB, long batC, long batO, int ldo, int coff)
{
    const int m0 = (SWAPXY ? blockIdx.x : blockIdx.y) * 128;
    const int n0 = (SWAPXY ? blockIdx.y : blockIdx.x) * 128;
    if (CAUSAL && n0 > m0 + 127) return;    // tile fully above the causal diagonal

    extern __shared__ char dsm[];
    const uint32_t sbase = smem_u32(dsm);

    const int tid  = threadIdx.x;
    const int wid  = tid >> 5;
    const int lane = tid & 31;
    const int warp_m = wid & 1;
    const int warp_n = wid >> 1;
    const int z  = blockIdx.z;
    A += (long)z * batA;
    B += (long)z * batB;

    float acc[4][4][4];
#pragma unroll
    for (int i = 0; i < 4; i++)
#pragma unroll
        for (int j = 0; j < 4; j++)
#pragma unroll
            for (int r = 0; r < 4; r++) acc[i][j][r] = 0.f;

    const int a_r = lane & 15;
    const int a_c = ((lane >> 4) & 1) * 8;
    const int b_r = (lane & 7) + ((lane >> 4) & 1) * 8;
    const int b_c = ((lane >> 3) & 1) * 8;

    const int lrow = tid >> 1;
    const int lhalf = (tid & 1);
    const uint32_t dstrow = (uint32_t)(lrow * 80 + lhalf * 32);

    const int Keff = CK ? ((m0 + 128) < K ? (m0 + 128) : K) : K;
    const int nchunks = Keff / 32;

    auto issue = [&](int ch, int buf) {
        const long ka = (long)(m0 + lrow) * K + (long)ch * 32 + lhalf * 16;
        const long kb = (long)(n0 + lrow) * K + (long)ch * 32 + lhalf * 16;
        uint32_t d = sbase + buf * STG + dstrow;
        cp16(d,              A + ka);  cp16(d + 16,          A + ka + 8);
        cp16(d + OFF_B,      B + kb);  cp16(d + OFF_B + 16,  B + kb + 8);
    };

    issue(0, 0);
    CP_COMMIT();

    for (int ch = 0; ch < nchunks; ch++) {
        const int buf = ch & 1;
        if (ch + 1 < nchunks) {
            issue(ch + 1, buf ^ 1);
            CP_COMMIT();
            CP_WAIT1();
        } else {
            CP_WAIT0();
        }
        __syncthreads();

        const uint32_t uA = sbase + buf * STG;
        const uint32_t uB = uA + OFF_B;

#pragma unroll
        for (int ks = 0; ks < 2; ks++) {
            uint32_t am[4][4];
#pragma unroll
            for (int ma = 0; ma < 4; ma++) {
                uint32_t off = ((warp_m * 64 + ma * 16 + a_r) * LDS + ks * 16 + a_c) * 2;
                ldm_x4(am[ma], uA + off);
            }
            uint32_t bm[4][2];
#pragma unroll
            for (int np = 0; np < 2; np++) {
                uint32_t off = ((warp_n * 32 + np * 16 + b_r) * LDS + ks * 16 + b_c) * 2;
                uint32_t t[4];
                ldm_x4(t, uB + off);
                bm[np*2][0]   = t[0]; bm[np*2][1]   = t[1];
                bm[np*2+1][0] = t[2]; bm[np*2+1][1] = t[3];
            }
#pragma unroll
            for (int ma = 0; ma < 4; ma++)
#pragma unroll
                for (int na = 0; na < 4; na++)
                    mma16816(acc[ma][na], am[ma], bm[na]);
        }
        __syncthreads();
    }

    if (OMODE == 0) C += (long)z * batC;
    else            O += (long)z * batO;

#pragma unroll
    for (int ma = 0; ma < 4; ma++) {
        const int row0 = m0 + warp_m * 64 + ma * 16 + (lane >> 2);
#pragma unroll
        for (int na = 0; na < 4; na++) {
            const int col = n0 + warp_n * 32 + na * 8 + (lane & 3) * 2;
            float2 v0 = make_float2(acc[ma][na][0], acc[ma][na][1]);
            float2 v1 = make_float2(acc[ma][na][2], acc[ma][na][3]);
            if (BIAS) {
                float2 bb = *reinterpret_cast<const float2*>(bias + col);
                v0.x += bb.x; v0.y += bb.y; v1.x += bb.x; v1.y += bb.y;
            }
            if (TANH_ACT) {
                v0.x = tanhf(v0.x); v0.y = tanhf(v0.y);
                v1.x = tanhf(v1.x); v1.y = tanhf(v1.y);
            }
            if (OMODE == 0) {
                *reinterpret_cast<float2*>(C + (long)row0 * N + col)       = v0;
                *reinterpret_cast<float2*>(C + (long)(row0 + 8) * N + col) = v1;
            } else {
                long o0 = (long)row0 * ldo + coff + col;
                long o1 = (long)(row0 + 8) * ldo + coff + col;
                *reinterpret_cast<__half2*>(O + o0) =
                    __halves2half2(__float2half_rn(v0.x), __float2half_rn(v0.y));
                *reinterpret_cast<__half2*>(O + o1) =
                    __halves2half2(__float2half_rn(v1.x), __float2half_rn(v1.y));
            }
        }
    }
}

// ================= embedding gather + fp16 convert (also resets RNN barrier) =================
__global__ void __launch_bounds__(256)
emb_gather(const float* __restrict__ emb, const int* __restrict__ x, __half* __restrict__ eA)
{
    if (blockIdx.x == 0 && threadIdx.x == 0) g_bar = 0u;   // reset RNN grid barrier
    const long n8 = (long)MM * EE / 8;
    for (long i8 = (long)blockIdx.x * 256 + threadIdx.x; i8 < n8; i8 += (long)gridDim.x * 256) {
        long idx = i8 << 3;
        int row = (int)(idx >> 9);           // EE = 512
        int c   = (int)(idx & 511);
        long src = (long)x[row] * EE + c;
        float4 x0 = *reinterpret_cast<const float4*>(emb + src);
        float4 x1 = *reinterpret_cast<const float4*>(emb + src + 4);
        alignas(16) __half hv[8];
        hv[0] = __float2half_rn(x0.x); hv[1] = __float2half_rn(x0.y);
        hv[2] = __float2half_rn(x0.z); hv[3] = __float2half_rn(x0.w);
        hv[4] = __float2half_rn(x1.x); hv[5] = __float2half_rn(x1.y);
        hv[6] = __float2half_rn(x1.z); hv[7] = __float2half_rn(x1.w);
        *reinterpret_cast<uint4*>(eA + idx) = *reinterpret_cast<const uint4*>(hv);
    }
}

// ================= fp32 -> fp16: single read, dual layout write =================
__global__ void __launch_bounds__(256)
conv_R2(const float* __restrict__ in, __half* __restrict__ o1, __half* __restrict__ o2,
        long n, int ld2)
{
    const long n8 = n >> 3;
    for (long i8 = (long)blockIdx.x * 256 + threadIdx.x; i8 < n8; i8 += (long)gridDim.x * 256) {
        long idx = i8 << 3;
        long r = idx >> 10;
        int  c = (int)(idx & 1023);
        float4 x0 = *reinterpret_cast<const float4*>(in + idx);
        float4 x1 = *reinterpret_cast<const float4*>(in + idx + 4);
        alignas(16) __half hv[8];
        hv[0] = __float2half_rn(x0.x); hv[1] = __float2half_rn(x0.y);
        hv[2] = __float2half_rn(x0.z); hv[3] = __float2half_rn(x0.w);
        hv[4] = __float2half_rn(x1.x); hv[5] = __float2half_rn(x1.y);
        hv[6] = __float2half_rn(x1.z); hv[7] = __float2half_rn(x1.w);
        uint4 pk = *reinterpret_cast<const uint4*>(hv);
        *reinterpret_cast<uint4*>(o1 + idx)         = pk;
        *reinterpret_cast<uint4*>(o2 + r * ld2 + c) = pk;
    }
}

// transpose: in [R,C] fp32 -> out [C,R] fp16 (batched via z)
__global__ void __launch_bounds__(256)
conv_T(const float* __restrict__ in, __half* __restrict__ o, int R, int C, long batIn, long batOut)
{
    __shared__ float t[32][33];
    const int tx = threadIdx.x & 31, ty = threadIdx.x >> 5;
    const int x = blockIdx.x * 32 + tx;
    in += (long)blockIdx.z * batIn;
#pragma unroll
    for (int j = 0; j < 4; j++) {
        int y = blockIdx.y * 32 + ty + j * 8;
        t[ty + j * 8][tx] = in[(long)y * C + x];
    }
    __syncthreads();
    const int ox = blockIdx.y * 32 + tx;
    long ob = (long)blockIdx.z * batOut;
#pragma unroll
    for (int j = 0; j < 4; j++) {
        int oy = blockIdx.x * 32 + ty + j * 8;
        o[ob + (long)oy * R + ox] = __float2half_rn(t[tx][ty + j * 8]);
    }
}

// ================= RNN recurrence (persistent, 128 CTAs x 256 thr) =================
// Release/acquire grid barrier; pre[t] prefetched off the dependency chain.
#define RNN_CTAS 128

__device__ __forceinline__ void grid_barrier(unsigned phase)
{
    __syncthreads();
    if (threadIdx.x == 0) {
        asm volatile("red.release.gpu.global.add.u32 [%0], %1;"
                     :: "l"(&g_bar), "r"(1u) : "memory");
        const unsigned target = phase * RNN_CTAS;
        unsigned v;
        do {
            asm volatile("ld.acquire.gpu.global.u32 %0, [%1];"
                         : "=r"(v) : "l"(&g_bar) : "memory");
        } while (v < target);
    }
    __syncthreads();
}

__global__ void __launch_bounds__(256, 1)
rnn_kernel(const float* __restrict__ w_hh)
{
    const int c = blockIdx.x, tid = threadIdx.x;
    const int w = tid >> 5, l = tid & 31;
    const int j = c * 8 + w;
    float wr[32];
#pragma unroll
    for (int r = 0; r < 32; r++) wr[r] = w_hh[(long)(r * 32 + l) * HH + j];
    __shared__ float hsm[BB * HH];
    if (l == 0) {
#pragma unroll
        for (int b = 0; b < BB; b++) {
            float hv = tanhf(g_pre[((long)b * TT) * HH + j]);
            __stcg(&g_hbuf[1 * BB * HH + b * HH + j], hv);   // critical path first
            g_hs[((long)b * TT) * HH + j] = hv;
        }
    }
    grid_barrier(1);
    for (int t = 1; t < TT; t++) {
        // prefetch pre[t] (independent of h) so its latency overlaps staging+sync
        float pre_t[BB];
        if (l == 0) {
#pragma unroll
            for (int b = 0; b < BB; b++)
                pre_t[b] = __ldcg(&g_pre[((long)b * TT + t) * HH + j]);
        }

        const float4* src = reinterpret_cast<const float4*>(&g_hbuf[(t & 1) * BB * HH]);
        for (int i = tid; i < BB * HH / 4; i += 256)
            reinterpret_cast<float4*>(hsm)[i] = __ldcg(src + i);
        __syncthreads();
#pragma unroll
        for (int b = 0; b < BB; b++) {
            const float* hp = &hsm[b * HH];
            float s = 0.f;
#pragma unroll
            for (int r = 0; r < 32; r++) s = fmaf(wr[r], hp[r * 32 + l], s);
#pragma unroll
            for (int o = 16; o; o >>= 1) s += __shfl_xor_sync(0xffffffffu, s, o);
            if (l == 0) {
                float hv = tanhf(pre_t[b] + s);
                __stcg(&g_hbuf[((t + 1) & 1) * BB * HH + b * HH + j], hv);  // critical first
                g_hs[((long)b * TT + t) * HH + j] = hv;
            }
        }
        if (t < TT - 1) grid_barrier((unsigned)(t + 1));
    }
}

// ================= causal softmax (fused fp16 store of P) =================
__global__ void __launch_bounds__(256)
softmax_kernel(float* __restrict__ sc)
{
    const int row = blockIdx.x;
    const int t = row & (TT - 1);
    float* p = sc + (long)row * TT;
    __half* ph = g_pA + (long)row * TT;
    __shared__ float red[256];
    const int tid = threadIdx.x;
    const float scale = 1.0f / 32.0f;
    float mx = -1e30f;
    for (int s = tid; s <= t; s += 256) mx = fmaxf(mx, p[s]);
    red[tid] = mx; __syncthreads();
    for (int o = 128; o; o >>= 1) { if (tid < o) red[tid] = fmaxf(red[tid], red[tid + o]); __syncthreads(); }
    mx = red[0] * scale; __syncthreads();
    float sum = 0.f;
    for (int s = tid; s <= t; s += 256) { float e = expf(p[s] * scale - mx); p[s] = e; sum += e; }
    red[tid] = sum; __syncthreads();
    for (int o = 128; o; o >>= 1) { if (tid < o) red[tid] += red[tid + o]; __syncthreads(); }
    const float inv = 1.0f / red[0];
    const __half z16 = __float2half(0.f);
    for (int s = tid; s <= t; s += 256) ph[s] = __float2half_rn(p[s] * inv);
    for (int s = t + 1 + tid; s < TT; s += 256) ph[s] = z16;
}

// ================= launch =================
extern "C" void kernel_launch(void* const* d_in, const int* in_sizes, int n_in,
                              void* d_out, int out_size)
{
    (void)in_sizes; (void)n_in; (void)out_size;
    const int*   x      = (const int*)  d_in[0];
    const float* emb    = (const float*)d_in[1];
    const float* w_ih   = (const float*)d_in[2];
    const float* b_ih   = (const float*)d_in[3];
    const float* w_hh   = (const float*)d_in[4];
    const float* wq     = (const float*)d_in[5];
    const float* wk     = (const float*)d_in[6];
    const float* wv     = (const float*)d_in[7];
    const float* w_mix  = (const float*)d_in[8];
    const float* b_mix  = (const float*)d_in[9];
    const float* w_proj = (const float*)d_in[10];
    const float* b_proj = (const float*)d_in[11];
    float* out = (float*)d_out;

    float *pre, *hs, *v, *scores;
    cudaGetSymbolAddress((void**)&pre, g_pre);
    cudaGetSymbolAddress((void**)&hs, g_hs);
    cudaGetSymbolAddress((void**)&v, g_v);
    cudaGetSymbolAddress((void**)&scores, g_scores);

    __half *eA,*wihT,*hsA,*wqT,*wkT,*wvT,*qA,*kB,*pA,*vT,*mxA,*mxB,*prA,*prB;
    cudaGetSymbolAddress((void**)&eA,  g_eA);
    cudaGetSymbolAddress((void**)&wihT,g_wihT);
    cudaGetSymbolAddress((void**)&hsA, g_hsA);
    cudaGetSymbolAddress((void**)&wqT, g_wqT);
    cudaGetSymbolAddress((void**)&wkT, g_wkT);
    cudaGetSymbolAddress((void**)&wvT, g_wvT);
    cudaGetSymbolAddress((void**)&qA,  g_qA);
    cudaGetSymbolAddress((void**)&kB,  g_kB);
    cudaGetSymbolAddress((void**)&pA,  g_pA);
    cudaGetSymbolAddress((void**)&vT,  g_vT);
    cudaGetSymbolAddress((void**)&mxA, g_mixA);
    cudaGetSymbolAddress((void**)&mxB, g_mixB);
    cudaGetSymbolAddress((void**)&prA, g_prA);
    cudaGetSymbolAddress((void**)&prB, g_prB);

    cudaFuncSetAttribute(tgemm<0,false,false,false,false,false>, cudaFuncAttributeMaxDynamicSharedMemorySize, SMEM_PIPE);
    cudaFuncSetAttribute(tgemm<0,false,false,true,false,false>,  cudaFuncAttributeMaxDynamicSharedMemorySize, SMEM_PIPE);
    cudaFuncSetAttribute(tgemm<0,true,false,false,false,false>,  cudaFuncAttributeMaxDynamicSharedMemorySize, SMEM_PIPE);
    cudaFuncSetAttribute(tgemm<0,true,false,false,false,true>,   cudaFuncAttributeMaxDynamicSharedMemorySize, SMEM_PIPE);
    cudaFuncSetAttribute(tgemm<1,false,false,false,false,false>, cudaFuncAttributeMaxDynamicSharedMemorySize, SMEM_PIPE);
    cudaFuncSetAttribute(tgemm<1,false,false,false,true,false>,  cudaFuncAttributeMaxDynamicSharedMemorySize, SMEM_PIPE);
    cudaFuncSetAttribute(tgemm<1,true,true,false,false,false>,   cudaFuncAttributeMaxDynamicSharedMemorySize, SMEM_PIPE);

    dim3 blk(256);
    dim3 tblk(256);

    // 1) w_ih [E,H] -> wihT [H,E] fp16
    conv_T<<<dim3(HH/32, EE/32), tblk>>>(w_ih, wihT, EE, HH, 0, 0);
    // 2) eA = fp16(emb[x])  (also resets g_bar)
    emb_gather<<<1024, 256>>>(emb, x, eA);
    // 3) pre = eA @ wihT + b_ih  (fp16 tensor path, fp32 out)
    tgemm<0,true,false,false,false,false><<<dim3(HH/128, MM/128), blk, SMEM_PIPE>>>(
        eA, wihT, pre, nullptr, b_ih, MM, HH, EE, 0, 0, 0, 0, 0, 0);

    // 4) RNN -> hs (fp32)
    rnn_kernel<<<RNN_CTAS, 256>>>(w_hh);

    // conversions (off the recurrence critical path): hs -> hsA + mixA[:, :H] in one pass
    conv_R2<<<2048, 256>>>(hs, hsA, mxA, (long)MM*HH, 2*HH);
    conv_T<<<dim3(HH/32, HH/32), tblk>>>(wq, wqT, HH, HH, 0, 0);
    conv_T<<<dim3(HH/32, HH/32), tblk>>>(wk, wkT, HH, HH, 0, 0);
    conv_T<<<dim3(HH/32, HH/32), tblk>>>(wv, wvT, HH, HH, 0, 0);

    // q,k (fp16 out), v (fp32 for transpose)
    tgemm<1,false,false,false,false,false><<<dim3(HH/128, MM/128), blk, SMEM_PIPE>>>(
        hsA, wqT, nullptr, qA, nullptr, MM, HH, HH, 0, 0, 0, 0, HH, 0);
    tgemm<1,false,false,false,false,false><<<dim3(HH/128, MM/128), blk, SMEM_PIPE>>>(
        hsA, wkT, nullptr, kB, nullptr, MM, HH, HH, 0, 0, 0, 0, HH, 0);
    tgemm<0,false,false,false,false,false><<<dim3(HH/128, MM/128), blk, SMEM_PIPE>>>(
        hsA, wvT, v, nullptr, nullptr, MM, HH, HH, 0, 0, 0, 0, 0, 0);

    // scores = q @ k^T (fp32 out, causal tile-skip)
    tgemm<0,false,false,true,false,false><<<dim3(TT/128, TT/128, BB), blk, SMEM_PIPE>>>(
        qA, kB, scores, nullptr, nullptr, TT, TT, HH,
        (long)TT*HH, (long)TT*HH, (long)TT*TT, 0, 0, 0);

    // softmax (scale + causal + fp16 P)
    softmax_kernel<<<MM, 256>>>(scores);

    // ctx = P @ V  (causal K-limit) -> fp16 directly into mixA[:, H:2H]
    conv_T<<<dim3(HH/32, TT/32, BB), tblk>>>(v, vT, TT, HH, (long)TT*HH, (long)HH*TT);
    tgemm<1,false,false,false,true,false><<<dim3(HH/128, TT/128, BB), blk, SMEM_PIPE>>>(
        pA, vT, nullptr, mxA, nullptr, TT, HH, TT,
        (long)TT*TT, (long)HH*TT, 0, (long)TT*2*HH, 2*HH, HH);

    // h2 = tanh([hs|ctx] @ w_mix + b_mix) -> fp16 into prA
    conv_T<<<dim3(HH/32, 2*HH/32), tblk>>>(w_mix, mxB, 2*HH, HH, 0, 0);
    tgemm<1,true,true,false,false,false><<<dim3(HH/128, MM/128), blk, SMEM_PIPE>>>(
        mxA, mxB, nullptr, prA, b_mix, MM, HH, 2*HH, 0, 0, 0, 0, HH, 0);

    // out = h2 @ w_proj + b_proj   (SWAPXY, fp32-acc MMA — FACC reverted)
    conv_T<<<dim3(VV/32, HH/32), tblk>>>(w_proj, prB, HH, VV, 0, 0);
    tgemm<0,true,false,false,false,true><<<dim3(MM/128, VV/128), blk, SMEM_PIPE>>>(
        prA, prB, out, nullptr, b_proj, MM, VV, HH, 0, 0, 0, 0, 0, 0);
}